// round 2
// baseline (speedup 1.0000x reference)
#include <cuda_runtime.h>

// Problem constants (fixed by the reference)
constexpr int NB   = 32;   // neighbors per query
constexpr int A    = 4;    // anchors
constexpr int K    = 15;   // kernel points
constexpr int KP   = 16;   // padded K
constexpr int CIN  = 32;
constexpr int COUT = 32;
constexpr float INV_EXT = 1.0f / 0.6f;   // 1 / KP_EXTENT

// Tiny precomputed tables: rotated kernel points + their squared norms
__device__ float g_rot_kp[A][K][3];
__device__ float g_k2[A][K];

__global__ void precompute_kernel(const float* __restrict__ kp,
                                  const float* __restrict__ anchors) {
    int idx = threadIdx.x;
    if (idx < A * K) {
        int a = idx / K;
        int k = idx - a * K;
        float p0 = kp[k * 3 + 0], p1 = kp[k * 3 + 1], p2 = kp[k * 3 + 2];
        const float* R = anchors + a * 9;
        float r0 = R[0] * p0 + R[1] * p1 + R[2] * p2;
        float r1 = R[3] * p0 + R[4] * p1 + R[5] * p2;
        float r2 = R[6] * p0 + R[7] * p1 + R[8] * p2;
        g_rot_kp[a][k][0] = r0;
        g_rot_kp[a][k][1] = r1;
        g_rot_kp[a][k][2] = r2;
        g_k2[a][k] = r0 * r0 + r1 * r1 + r2 * r2;
    }
}

// One block per query point. 4 warps, warp w handles anchor a = w.
__global__ __launch_bounds__(128, 8) void kpconv_kernel(
    const float* __restrict__ q_pts,    // [N,3]
    const float* __restrict__ s_pts,    // [M,3]
    const int*   __restrict__ nbr,      // [N,NB]
    const float* __restrict__ x,        // [M,A,CIN]
    const float* __restrict__ weights,  // [K,CIN,COUT]
    float*       __restrict__ out)      // [N,A,COUT]
{
    const int n    = blockIdx.x;
    const int tid  = threadIdx.x;
    const int a    = tid >> 5;
    const int lane = tid & 31;

    __shared__ float s_diff[NB][3];
    __shared__ float s_n2[NB];
    __shared__ int   s_ind[NB];
    __shared__ float s_w[A][NB][KP];       // KP influence weights, padded
    __shared__ float s_wf[A][K][CIN];      // weighted features

    // ---- neighbor gather + centering (warp 0 lanes, 1 neighbor each) ----
    if (tid < NB) {
        int m = nbr[n * NB + tid];
        s_ind[tid] = m;
        float dx = s_pts[m * 3 + 0] - q_pts[n * 3 + 0];
        float dy = s_pts[m * 3 + 1] - q_pts[n * 3 + 1];
        float dz = s_pts[m * 3 + 2] - q_pts[n * 3 + 2];
        s_diff[tid][0] = dx;
        s_diff[tid][1] = dy;
        s_diff[tid][2] = dz;
        s_n2[tid] = dx * dx + dy * dy + dz * dz;
    }
    __syncthreads();

    // ---- KP influence weights: lane = neighbor b, loop over k ----
    {
        float dx = s_diff[lane][0];
        float dy = s_diff[lane][1];
        float dz = s_diff[lane][2];
        float n2 = s_n2[lane];
        #pragma unroll
        for (int k = 0; k < K; k++) {
            float r0 = g_rot_kp[a][k][0];
            float r1 = g_rot_kp[a][k][1];
            float r2 = g_rot_kp[a][k][2];
            float cross = dx * r0 + dy * r1 + dz * r2;
            float sq = n2 + g_k2[a][k] - 2.0f * cross;
            sq = fmaxf(sq, 1e-12f);
            float w = fmaxf(1.0f - sqrtf(sq) * INV_EXT, 0.0f);
            s_w[a][lane][k] = w;
        }
        s_w[a][lane][K] = 0.0f;  // pad
    }
    __syncwarp();

    // ---- Stage 1: weighted feature accumulation. lane = input channel c ----
    float wf[K];
    #pragma unroll
    for (int k = 0; k < K; k++) wf[k] = 0.0f;

    #pragma unroll 4
    for (int b = 0; b < NB; b++) {
        // coalesced 128B gather per warp; streaming hint keeps L1 for weights
        float xv = __ldcs(&x[((long)s_ind[b] * A + a) * CIN + lane]);
        const float4* wp = reinterpret_cast<const float4*>(&s_w[a][b][0]);
        float4 w0 = wp[0], w1 = wp[1], w2 = wp[2], w3 = wp[3];
        wf[0]  = fmaf(w0.x, xv, wf[0]);
        wf[1]  = fmaf(w0.y, xv, wf[1]);
        wf[2]  = fmaf(w0.z, xv, wf[2]);
        wf[3]  = fmaf(w0.w, xv, wf[3]);
        wf[4]  = fmaf(w1.x, xv, wf[4]);
        wf[5]  = fmaf(w1.y, xv, wf[5]);
        wf[6]  = fmaf(w1.z, xv, wf[6]);
        wf[7]  = fmaf(w1.w, xv, wf[7]);
        wf[8]  = fmaf(w2.x, xv, wf[8]);
        wf[9]  = fmaf(w2.y, xv, wf[9]);
        wf[10] = fmaf(w2.z, xv, wf[10]);
        wf[11] = fmaf(w2.w, xv, wf[11]);
        wf[12] = fmaf(w3.x, xv, wf[12]);
        wf[13] = fmaf(w3.y, xv, wf[13]);
        wf[14] = fmaf(w3.z, xv, wf[14]);
    }

    #pragma unroll
    for (int k = 0; k < K; k++) s_wf[a][k][lane] = wf[k];
    __syncwarp();

    // ---- Stage 2: [K*CIN] x [K*CIN, COUT] GEMV. lane = output channel d ----
    float acc = 0.0f;
    for (int k = 0; k < K; k++) {
        const float* wrow = weights + k * CIN * COUT + lane;
        #pragma unroll
        for (int c = 0; c < CIN; c++) {
            acc = fmaf(s_wf[a][k][c], __ldg(&wrow[c * COUT]), acc);
        }
    }
    out[(n * A + a) * COUT + lane] = acc;
}

extern "C" void kernel_launch(void* const* d_in, const int* in_sizes, int n_in,
                              void* d_out, int out_size) {
    const float* q_pts   = (const float*)d_in[0];
    const float* s_pts   = (const float*)d_in[1];
    const int*   nbr     = (const int*)  d_in[2];
    const float* x       = (const float*)d_in[3];
    const float* kp      = (const float*)d_in[4];
    const float* anchors = (const float*)d_in[5];
    const float* weights = (const float*)d_in[6];
    float* out = (float*)d_out;

    const int Nq = in_sizes[2] / NB;   // 16000

    precompute_kernel<<<1, 64>>>(kp, anchors);
    kpconv_kernel<<<Nq, 128>>>(q_pts, s_pts, nbr, x, weights, out);
}

// round 3
// speedup vs baseline: 1.0593x; 1.0593x over previous
#include <cuda_runtime.h>

// Problem constants (fixed by the reference)
constexpr int NB   = 32;   // neighbors per query
constexpr int A    = 4;    // anchors
constexpr int K    = 15;   // kernel points
constexpr int CIN  = 32;
constexpr int COUT = 32;
constexpr int QB   = 8;            // queries per block
constexpr int ROWS = QB * A;       // 32 output rows per block
constexpr int KC   = K * CIN;      // 480 reduction length for stage 2
constexpr int WF_STRIDE = KC + 4;  // 484: odd in float4 units -> conflict-free LDS.128
constexpr int SW_STRIDE = 20;      // padded influence row (floats), 16B-aligned
constexpr float INV_EXT = 1.0f / 0.6f;

// Precomputed rotated kernel points + squared norms
__device__ float g_rot_kp[A][K][3];
__device__ float g_k2[A][K];

__global__ void precompute_kernel(const float* __restrict__ kp,
                                  const float* __restrict__ anchors) {
    int idx = threadIdx.x;
    if (idx < A * K) {
        int a = idx / K;
        int k = idx - a * K;
        float p0 = kp[k * 3 + 0], p1 = kp[k * 3 + 1], p2 = kp[k * 3 + 2];
        const float* R = anchors + a * 9;
        float r0 = R[0] * p0 + R[1] * p1 + R[2] * p2;
        float r1 = R[3] * p0 + R[4] * p1 + R[5] * p2;
        float r2 = R[6] * p0 + R[7] * p1 + R[8] * p2;
        g_rot_kp[a][k][0] = r0;
        g_rot_kp[a][k][1] = r1;
        g_rot_kp[a][k][2] = r2;
        g_k2[a][k] = r0 * r0 + r1 * r1 + r2 * r2;
    }
}

// 256 threads = 8 warps. Warp w handles query n0+w for stages 0/1 (all 4
// anchors sequentially), then warp w handles output-column chunk d=4w..4w+3
// of the block's 32x480 @ 480x32 stage-2 GEMM.
__global__ __launch_bounds__(256, 2) void kpconv_kernel(
    const float* __restrict__ q_pts,    // [N,3]
    const float* __restrict__ s_pts,    // [M,3]
    const int*   __restrict__ nbr,      // [N,NB]
    const float* __restrict__ x,        // [M,A,CIN]
    const float* __restrict__ weights,  // [K,CIN,COUT]
    float*       __restrict__ out)      // [N,A,COUT]
{
    extern __shared__ float sm[];
    float* s_wf = sm;                                  // [ROWS][WF_STRIDE]
    float* s_w  = sm + ROWS * WF_STRIDE;               // [8 warps][NB][SW_STRIDE]
    int*   s_ind = (int*)(s_w + 8 * NB * SW_STRIDE);   // [8 warps][NB]

    const int tid  = threadIdx.x;
    const int w    = tid >> 5;
    const int lane = tid & 31;
    const int n0   = blockIdx.x * QB;
    const int q    = n0 + w;

    // ---- stage 0: neighbor gather + centering (lane = neighbor b) ----
    int m = nbr[q * NB + lane];
    s_ind[w * NB + lane] = m;
    float qx = q_pts[q * 3 + 0];
    float qy = q_pts[q * 3 + 1];
    float qz = q_pts[q * 3 + 2];
    float dx = s_pts[m * 3 + 0] - qx;
    float dy = s_pts[m * 3 + 1] - qy;
    float dz = s_pts[m * 3 + 2] - qz;
    float n2 = dx * dx + dy * dy + dz * dz;

    float* sww = s_w + w * NB * SW_STRIDE;
    const int* sii = s_ind + w * NB;

    #pragma unroll 1
    for (int a = 0; a < A; a++) {
        // ---- influence weights for this anchor (lane = b) ----
        float wk[16];
        #pragma unroll
        for (int k = 0; k < K; k++) {
            float r0 = g_rot_kp[a][k][0];
            float r1 = g_rot_kp[a][k][1];
            float r2 = g_rot_kp[a][k][2];
            float cross = dx * r0 + dy * r1 + dz * r2;
            float sq = n2 + g_k2[a][k] - 2.0f * cross;
            sq = fmaxf(sq, 1e-12f);
            wk[k] = fmaxf(1.0f - sqrtf(sq) * INV_EXT, 0.0f);
        }
        wk[15] = 0.0f;
        {
            float4* dst = (float4*)(sww + lane * SW_STRIDE);
            dst[0] = make_float4(wk[0],  wk[1],  wk[2],  wk[3]);
            dst[1] = make_float4(wk[4],  wk[5],  wk[6],  wk[7]);
            dst[2] = make_float4(wk[8],  wk[9],  wk[10], wk[11]);
            dst[3] = make_float4(wk[12], wk[13], wk[14], wk[15]);
        }
        __syncwarp();

        // ---- stage 1: weighted feature accumulation (lane = channel c) ----
        float wf[K];
        #pragma unroll
        for (int k = 0; k < K; k++) wf[k] = 0.0f;

        #pragma unroll 4
        for (int b = 0; b < NB; b++) {
            float xv = __ldcs(&x[((long)sii[b] * A + a) * CIN + lane]);
            const float4* wp = (const float4*)(sww + b * SW_STRIDE);
            float4 w0 = wp[0], w1 = wp[1], w2 = wp[2], w3 = wp[3];
            wf[0]  = fmaf(w0.x, xv, wf[0]);
            wf[1]  = fmaf(w0.y, xv, wf[1]);
            wf[2]  = fmaf(w0.z, xv, wf[2]);
            wf[3]  = fmaf(w0.w, xv, wf[3]);
            wf[4]  = fmaf(w1.x, xv, wf[4]);
            wf[5]  = fmaf(w1.y, xv, wf[5]);
            wf[6]  = fmaf(w1.z, xv, wf[6]);
            wf[7]  = fmaf(w1.w, xv, wf[7]);
            wf[8]  = fmaf(w2.x, xv, wf[8]);
            wf[9]  = fmaf(w2.y, xv, wf[9]);
            wf[10] = fmaf(w2.z, xv, wf[10]);
            wf[11] = fmaf(w2.w, xv, wf[11]);
            wf[12] = fmaf(w3.x, xv, wf[12]);
            wf[13] = fmaf(w3.y, xv, wf[13]);
            wf[14] = fmaf(w3.z, xv, wf[14]);
        }

        // store wf transposed into block-shared s_wf[row][kc]
        {
            int row = w * A + a;
            float* dwf = s_wf + row * WF_STRIDE + lane;
            #pragma unroll
            for (int k = 0; k < K; k++) dwf[k * CIN] = wf[k];
        }
        __syncwarp();
    }
    __syncthreads();

    // ---- stage 2: block GEMM [32 rows x 480] @ [480 x 32].
    // Warp w owns output columns dc..dc+3; lane = row. Per 4 kc:
    // 1 conflict-free LDS.128 (wf) + 4 broadcast LDG.128 (weights) + 16 FMA.
    const int dc = w * 4;
    const float* wfp = s_wf + lane * WF_STRIDE;

    // 8 independent accumulators for ILP (2 partial sums per output)
    float ax0 = 0.f, ax1 = 0.f, ay0 = 0.f, ay1 = 0.f;
    float az0 = 0.f, az1 = 0.f, aw0 = 0.f, aw1 = 0.f;

    #pragma unroll 4
    for (int kc = 0; kc < KC; kc += 4) {
        float4 f  = *(const float4*)(wfp + kc);
        float4 w0 = __ldg((const float4*)(weights + (kc + 0) * COUT + dc));
        float4 w1 = __ldg((const float4*)(weights + (kc + 1) * COUT + dc));
        float4 w2 = __ldg((const float4*)(weights + (kc + 2) * COUT + dc));
        float4 w3 = __ldg((const float4*)(weights + (kc + 3) * COUT + dc));
        ax0 = fmaf(f.x, w0.x, ax0);
        ax1 = fmaf(f.y, w1.x, ax1);
        ax0 = fmaf(f.z, w2.x, ax0);
        ax1 = fmaf(f.w, w3.x, ax1);
        ay0 = fmaf(f.x, w0.y, ay0);
        ay1 = fmaf(f.y, w1.y, ay1);
        ay0 = fmaf(f.z, w2.y, ay0);
        ay1 = fmaf(f.w, w3.y, ay1);
        az0 = fmaf(f.x, w0.z, az0);
        az1 = fmaf(f.y, w1.z, az1);
        az0 = fmaf(f.z, w2.z, az0);
        az1 = fmaf(f.w, w3.z, az1);
        aw0 = fmaf(f.x, w0.w, aw0);
        aw1 = fmaf(f.y, w1.w, aw1);
        aw0 = fmaf(f.z, w2.w, aw0);
        aw1 = fmaf(f.w, w3.w, aw1);
    }

    float4 o = make_float4(ax0 + ax1, ay0 + ay1, az0 + az1, aw0 + aw1);
    // global row = blockIdx.x*32 + lane; out layout [N,A,COUT] with row = n*A+a
    *(float4*)(out + ((long)blockIdx.x * ROWS + lane) * COUT + dc) = o;
}

extern "C" void kernel_launch(void* const* d_in, const int* in_sizes, int n_in,
                              void* d_out, int out_size) {
    const float* q_pts   = (const float*)d_in[0];
    const float* s_pts   = (const float*)d_in[1];
    const int*   nbr     = (const int*)  d_in[2];
    const float* x       = (const float*)d_in[3];
    const float* kp      = (const float*)d_in[4];
    const float* anchors = (const float*)d_in[5];
    const float* weights = (const float*)d_in[6];
    float* out = (float*)d_out;

    const int Nq = in_sizes[2] / NB;   // 16000

    size_t smem = (size_t)(ROWS * WF_STRIDE + 8 * NB * SW_STRIDE) * sizeof(float)
                + (size_t)(8 * NB) * sizeof(int);
    static bool attr_set = false;
    if (!attr_set) {
        cudaFuncSetAttribute(kpconv_kernel,
                             cudaFuncAttributeMaxDynamicSharedMemorySize,
                             (int)smem);
        attr_set = true;
    }

    precompute_kernel<<<1, 64>>>(kp, anchors);
    kpconv_kernel<<<Nq / QB, 256, smem>>>(q_pts, s_pts, nbr, x, weights, out);
}

// round 4
// speedup vs baseline: 1.0614x; 1.0020x over previous
#include <cuda_runtime.h>

// Problem constants (fixed by the reference)
constexpr int NB   = 32;   // neighbors per query
constexpr int A    = 4;    // anchors
constexpr int K    = 15;   // kernel points
constexpr int CIN  = 32;
constexpr int COUT = 32;
constexpr int QB   = 8;            // queries per block
constexpr int ROWS = QB * A;       // 32 output rows per block
constexpr int KC   = K * CIN;      // 480 reduction length for stage 2
constexpr int WF_STRIDE = KC + 4;  // 484: odd in float4 units -> conflict-free LDS.128
constexpr int SW_STRIDE = 20;      // padded influence row (floats), 16B-aligned
constexpr float INV_EXT = 1.0f / 0.6f;

// Precomputed rotated kernel points + squared norms
__device__ float g_rot_kp[A][K][3];
__device__ float g_k2[A][K];

__global__ void precompute_kernel(const float* __restrict__ kp,
                                  const float* __restrict__ anchors) {
    int idx = threadIdx.x;
    if (idx < A * K) {
        int a = idx / K;
        int k = idx - a * K;
        float p0 = kp[k * 3 + 0], p1 = kp[k * 3 + 1], p2 = kp[k * 3 + 2];
        const float* R = anchors + a * 9;
        float r0 = R[0] * p0 + R[1] * p1 + R[2] * p2;
        float r1 = R[3] * p0 + R[4] * p1 + R[5] * p2;
        float r2 = R[6] * p0 + R[7] * p1 + R[8] * p2;
        g_rot_kp[a][k][0] = r0;
        g_rot_kp[a][k][1] = r1;
        g_rot_kp[a][k][2] = r2;
        g_k2[a][k] = r0 * r0 + r1 * r1 + r2 * r2;
    }
}

// 256 threads = 8 warps. Warp w handles query n0+w for stages 0/1 (all 4
// anchors sequentially), then warp w handles output-column chunk d=4w..4w+3
// of the block's 32x480 @ 480x32 stage-2 GEMM.
__global__ __launch_bounds__(256, 2) void kpconv_kernel(
    const float* __restrict__ q_pts,    // [N,3]
    const float* __restrict__ s_pts,    // [M,3]
    const int*   __restrict__ nbr,      // [N,NB]
    const float* __restrict__ x,        // [M,A,CIN]
    const float* __restrict__ weights,  // [K,CIN,COUT]
    float*       __restrict__ out)      // [N,A,COUT]
{
    extern __shared__ float sm[];
    float* s_wf = sm;                                  // [ROWS][WF_STRIDE]
    float* s_w  = sm + ROWS * WF_STRIDE;               // [8 warps][NB][SW_STRIDE]
    int*   s_ind = (int*)(s_w + 8 * NB * SW_STRIDE);   // [8 warps][NB]

    const int tid  = threadIdx.x;
    const int w    = tid >> 5;
    const int lane = tid & 31;
    const int n0   = blockIdx.x * QB;
    const int q    = n0 + w;

    // ---- stage 0: neighbor gather + centering (lane = neighbor b) ----
    int m = nbr[q * NB + lane];
    s_ind[w * NB + lane] = m;
    float qx = q_pts[q * 3 + 0];
    float qy = q_pts[q * 3 + 1];
    float qz = q_pts[q * 3 + 2];
    float dx = s_pts[m * 3 + 0] - qx;
    float dy = s_pts[m * 3 + 1] - qy;
    float dz = s_pts[m * 3 + 2] - qz;
    float n2 = dx * dx + dy * dy + dz * dz;

    float* sww = s_w + w * NB * SW_STRIDE;
    const int* sii = s_ind + w * NB;

    #pragma unroll 1
    for (int a = 0; a < A; a++) {
        // ---- influence weights for this anchor (lane = b) ----
        float wk[16];
        #pragma unroll
        for (int k = 0; k < K; k++) {
            float r0 = g_rot_kp[a][k][0];
            float r1 = g_rot_kp[a][k][1];
            float r2 = g_rot_kp[a][k][2];
            float cross = dx * r0 + dy * r1 + dz * r2;
            float sq = n2 + g_k2[a][k] - 2.0f * cross;
            sq = fmaxf(sq, 1e-12f);
            wk[k] = fmaxf(1.0f - sqrtf(sq) * INV_EXT, 0.0f);
        }
        wk[15] = 0.0f;
        {
            float4* dst = (float4*)(sww + lane * SW_STRIDE);
            dst[0] = make_float4(wk[0],  wk[1],  wk[2],  wk[3]);
            dst[1] = make_float4(wk[4],  wk[5],  wk[6],  wk[7]);
            dst[2] = make_float4(wk[8],  wk[9],  wk[10], wk[11]);
            dst[3] = make_float4(wk[12], wk[13], wk[14], wk[15]);
        }
        __syncwarp();

        // ---- stage 1: weighted feature accumulation (lane = channel c) ----
        float wf[K];
        #pragma unroll
        for (int k = 0; k < K; k++) wf[k] = 0.0f;

        #pragma unroll 4
        for (int b = 0; b < NB; b++) {
            float xv = __ldcs(&x[((long)sii[b] * A + a) * CIN + lane]);
            const float4* wp = (const float4*)(sww + b * SW_STRIDE);
            float4 w0 = wp[0], w1 = wp[1], w2 = wp[2], w3 = wp[3];
            wf[0]  = fmaf(w0.x, xv, wf[0]);
            wf[1]  = fmaf(w0.y, xv, wf[1]);
            wf[2]  = fmaf(w0.z, xv, wf[2]);
            wf[3]  = fmaf(w0.w, xv, wf[3]);
            wf[4]  = fmaf(w1.x, xv, wf[4]);
            wf[5]  = fmaf(w1.y, xv, wf[5]);
            wf[6]  = fmaf(w1.z, xv, wf[6]);
            wf[7]  = fmaf(w1.w, xv, wf[7]);
            wf[8]  = fmaf(w2.x, xv, wf[8]);
            wf[9]  = fmaf(w2.y, xv, wf[9]);
            wf[10] = fmaf(w2.z, xv, wf[10]);
            wf[11] = fmaf(w2.w, xv, wf[11]);
            wf[12] = fmaf(w3.x, xv, wf[12]);
            wf[13] = fmaf(w3.y, xv, wf[13]);
            wf[14] = fmaf(w3.z, xv, wf[14]);
        }

        // store wf transposed into block-shared s_wf[row][kc]
        {
            int row = w * A + a;
            float* dwf = s_wf + row * WF_STRIDE + lane;
            #pragma unroll
            for (int k = 0; k < K; k++) dwf[k * CIN] = wf[k];
        }
        __syncwarp();
    }
    __syncthreads();

    // ---- stage 2: block GEMM [32 rows x 480] @ [480 x 32].
    // Warp w owns output columns dc..dc+3; lane = row. Per 4 kc:
    // 1 conflict-free LDS.128 (wf) + 4 broadcast LDG.128 (weights) + 16 FMA.
    const int dc = w * 4;
    const float* wfp = s_wf + lane * WF_STRIDE;

    // 8 independent accumulators for ILP (2 partial sums per output)
    float ax0 = 0.f, ax1 = 0.f, ay0 = 0.f, ay1 = 0.f;
    float az0 = 0.f, az1 = 0.f, aw0 = 0.f, aw1 = 0.f;

    #pragma unroll 4
    for (int kc = 0; kc < KC; kc += 4) {
        float4 f  = *(const float4*)(wfp + kc);
        float4 w0 = __ldg((const float4*)(weights + (kc + 0) * COUT + dc));
        float4 w1 = __ldg((const float4*)(weights + (kc + 1) * COUT + dc));
        float4 w2 = __ldg((const float4*)(weights + (kc + 2) * COUT + dc));
        float4 w3 = __ldg((const float4*)(weights + (kc + 3) * COUT + dc));
        ax0 = fmaf(f.x, w0.x, ax0);
        ax1 = fmaf(f.y, w1.x, ax1);
        ax0 = fmaf(f.z, w2.x, ax0);
        ax1 = fmaf(f.w, w3.x, ax1);
        ay0 = fmaf(f.x, w0.y, ay0);
        ay1 = fmaf(f.y, w1.y, ay1);
        ay0 = fmaf(f.z, w2.y, ay0);
        ay1 = fmaf(f.w, w3.y, ay1);
        az0 = fmaf(f.x, w0.z, az0);
        az1 = fmaf(f.y, w1.z, az1);
        az0 = fmaf(f.z, w2.z, az0);
        az1 = fmaf(f.w, w3.z, az1);
        aw0 = fmaf(f.x, w0.w, aw0);
        aw1 = fmaf(f.y, w1.w, aw1);
        aw0 = fmaf(f.z, w2.w, aw0);
        aw1 = fmaf(f.w, w3.w, aw1);
    }

    float4 o = make_float4(ax0 + ax1, ay0 + ay1, az0 + az1, aw0 + aw1);
    // global row = blockIdx.x*32 + lane; out layout [N,A,COUT] with row = n*A+a
    *(float4*)(out + ((long)blockIdx.x * ROWS + lane) * COUT + dc) = o;
}

extern "C" void kernel_launch(void* const* d_in, const int* in_sizes, int n_in,
                              void* d_out, int out_size) {
    const float* q_pts   = (const float*)d_in[0];
    const float* s_pts   = (const float*)d_in[1];
    const int*   nbr     = (const int*)  d_in[2];
    const float* x       = (const float*)d_in[3];
    const float* kp      = (const float*)d_in[4];
    const float* anchors = (const float*)d_in[5];
    const float* weights = (const float*)d_in[6];
    float* out = (float*)d_out;

    const int Nq = in_sizes[2] / NB;   // 16000

    size_t smem = (size_t)(ROWS * WF_STRIDE + 8 * NB * SW_STRIDE) * sizeof(float)
                + (size_t)(8 * NB) * sizeof(int);
    static bool attr_set = false;
    if (!attr_set) {
        cudaFuncSetAttribute(kpconv_kernel,
                             cudaFuncAttributeMaxDynamicSharedMemorySize,
                             (int)smem);
        attr_set = true;
    }

    precompute_kernel<<<1, 64>>>(kp, anchors);
    kpconv_kernel<<<Nq / QB, 256, smem>>>(q_pts, s_pts, nbr, x, weights, out);
}

// round 5
// speedup vs baseline: 1.1024x; 1.0386x over previous
#include <cuda_runtime.h>

// Problem constants (fixed by the reference)
constexpr int NB   = 32;   // neighbors per query
constexpr int A    = 4;    // anchors
constexpr int K    = 15;   // kernel points
constexpr int CIN  = 32;
constexpr int COUT = 32;
constexpr int NQ   = 16000;
constexpr int ROWS_TOT = NQ * A;          // 64000 (n,a) rows
constexpr int KC   = K * CIN;             // 480 reduction length
constexpr int QB   = 8;                   // queries per block (kernel A)
constexpr int RB   = 32;                  // rows per block (kernel B)
constexpr int WF_PAD = KC + 4;            // 484 floats: stride 121 float4 (odd) -> conflict-free
constexpr int SW_STRIDE = 20;             // padded influence row
constexpr float INV_EXT = 1.0f / 0.6f;

// ---- device-global scratch / tables (no allocation allowed) ----
__device__ float g_wf[ROWS_TOT * KC];                 // stage-1 output, [na][kc]
__device__ float4 g_kp4[A * 16];                      // (r0,r1,r2,|kp|^2) per (a,k)
__device__ unsigned long long g_wp[(KC / 2) * COUT];  // (W[2p][d], W[2p+1][d]) packed

// ---- packed f32x2 helpers (bit-identical to scalar fp32 FMA) ----
__device__ __forceinline__ void fma2(unsigned long long& acc,
                                     unsigned long long a, unsigned long long b) {
    asm("fma.rn.f32x2 %0, %1, %2, %0;" : "+l"(acc) : "l"(a), "l"(b));
}
__device__ __forceinline__ unsigned long long dup2(float x) {
    unsigned long long r;
    asm("mov.b64 %0, {%1, %1};" : "=l"(r) : "f"(x));
    return r;
}
__device__ __forceinline__ float lo32(unsigned long long v) {
    float a, b; asm("mov.b64 {%0, %1}, %2;" : "=f"(a), "=f"(b) : "l"(v)); return a;
}
__device__ __forceinline__ float hi32(unsigned long long v) {
    float a, b; asm("mov.b64 {%0, %1}, %2;" : "=f"(a), "=f"(b) : "l"(v)); return b;
}

// ---- precompute: rotated kernel points + packed weight pairs ----
__global__ void precompute_kernel(const float* __restrict__ kp,
                                  const float* __restrict__ anchors,
                                  const float* __restrict__ weights) {
    int tid = threadIdx.x;
    if (tid < A * K) {
        int a = tid / K;
        int k = tid - a * K;
        float p0 = kp[k * 3 + 0], p1 = kp[k * 3 + 1], p2 = kp[k * 3 + 2];
        const float* R = anchors + a * 9;
        float r0 = R[0] * p0 + R[1] * p1 + R[2] * p2;
        float r1 = R[3] * p0 + R[4] * p1 + R[5] * p2;
        float r2 = R[6] * p0 + R[7] * p1 + R[8] * p2;
        g_kp4[a * 16 + k] = make_float4(r0, r1, r2, r0 * r0 + r1 * r1 + r2 * r2);
    }
    // pack weights: Wp[p][d] = (W[2p][d], W[2p+1][d]) ; W[kc][d] = weights[kc*32+d]
    for (int i = tid; i < (KC / 2) * COUT; i += blockDim.x) {
        int p = i >> 5;
        int d = i & 31;
        float lo = weights[(2 * p) * COUT + d];
        float hi = weights[(2 * p + 1) * COUT + d];
        unsigned long long v;
        asm("mov.b64 %0, {%1, %2};" : "=l"(v) : "f"(lo), "f"(hi));
        g_wp[i] = v;
    }
}

// =====================  Kernel A: stages 0+1  =====================
// 256 threads = 8 warps; warp w owns query blockIdx.x*8+w, loops 4 anchors.
// Writes wf[na][kc] (kc = k*32+c) to global scratch, coalesced.
__global__ __launch_bounds__(256, 4) void stage1_kernel(
    const float* __restrict__ q_pts,
    const float* __restrict__ s_pts,
    const int*   __restrict__ nbr,
    const float* __restrict__ x)
{
    __shared__ float4 s_kp[A * 16];
    __shared__ float  s_w[QB][NB][SW_STRIDE];
    __shared__ int    s_off[QB][NB];       // precomputed x row offsets (m*128)

    const int tid  = threadIdx.x;
    const int w    = tid >> 5;
    const int lane = tid & 31;
    const int q    = blockIdx.x * QB + w;

    if (tid < A * K) {
        int a = tid / K;
        int k = tid - a * K;
        s_kp[a * 16 + k] = g_kp4[a * 16 + k];
    }

    // stage 0: gather + center (lane = neighbor b)
    int m = nbr[q * NB + lane];
    s_off[w][lane] = m * (A * CIN);
    float dx = s_pts[m * 3 + 0] - q_pts[q * 3 + 0];
    float dy = s_pts[m * 3 + 1] - q_pts[q * 3 + 1];
    float dz = s_pts[m * 3 + 2] - q_pts[q * 3 + 2];
    float n2 = dx * dx + dy * dy + dz * dz;
    __syncthreads();

    #pragma unroll 1
    for (int a = 0; a < A; a++) {
        // influence weights (lane = b)
        {
            float wk[16];
            #pragma unroll
            for (int k = 0; k < K; k++) {
                float4 g = s_kp[a * 16 + k];
                float cross = dx * g.x + dy * g.y + dz * g.z;
                float sq = fmaxf(fmaf(-2.0f, cross, n2 + g.w), 1e-12f);
                wk[k] = fmaxf(1.0f - sqrtf(sq) * INV_EXT, 0.0f);
            }
            wk[15] = 0.0f;
            float4* dst = (float4*)&s_w[w][lane][0];
            dst[0] = make_float4(wk[0],  wk[1],  wk[2],  wk[3]);
            dst[1] = make_float4(wk[4],  wk[5],  wk[6],  wk[7]);
            dst[2] = make_float4(wk[8],  wk[9],  wk[10], wk[11]);
            dst[3] = make_float4(wk[12], wk[13], wk[14], wk[15]);
        }
        __syncwarp();

        // stage 1 (lane = channel c); accumulators pack (k, k+1)
        unsigned long long wf2[8];
        #pragma unroll
        for (int j = 0; j < 8; j++) wf2[j] = 0ULL;

        const float* xa = x + a * CIN + lane;
        #pragma unroll 4
        for (int b = 0; b < NB; b++) {
            float xv = __ldg(xa + s_off[w][b]);
            unsigned long long xv2 = dup2(xv);
            const ulonglong2* wp = (const ulonglong2*)&s_w[w][b][0];
            ulonglong2 p0 = wp[0], p1 = wp[1], p2 = wp[2], p3 = wp[3];
            fma2(wf2[0], p0.x, xv2);
            fma2(wf2[1], p0.y, xv2);
            fma2(wf2[2], p1.x, xv2);
            fma2(wf2[3], p1.y, xv2);
            fma2(wf2[4], p2.x, xv2);
            fma2(wf2[5], p2.y, xv2);
            fma2(wf2[6], p3.x, xv2);
            fma2(wf2[7], p3.y, xv2);
        }

        // store wf[na][k*32 + lane], coalesced (k=15 is pad, not stored)
        float* dst = g_wf + (q * A + a) * KC + lane;
        #pragma unroll
        for (int j = 0; j < 7; j++) {
            dst[(2 * j) * CIN]     = lo32(wf2[j]);
            dst[(2 * j + 1) * CIN] = hi32(wf2[j]);
        }
        dst[14 * CIN] = lo32(wf2[7]);
        __syncwarp();   // protect s_w before next anchor overwrites it
    }
}

// =====================  Kernel B: stage-2 GEMM  =====================
// [64000 x 480] @ [480 x 32]. Block = 32 rows, 256 threads = 8 warps.
// lane = row, warp w owns cols 4w..4w+3. Per 4 kc:
//   1 LDS.128 (wf pair-of-pairs) + 4 LDG.128 (packed weights) + 8 FFMA2.
__global__ __launch_bounds__(256, 3) void stage2_kernel(float* __restrict__ out)
{
    extern __shared__ float st[];   // [RB][WF_PAD]

    const int tid  = threadIdx.x;
    const int w    = tid >> 5;
    const int lane = tid & 31;

    // cooperative coalesced tile load: 32 rows x 480 floats = 3840 float4
    {
        const float4* src = (const float4*)(g_wf + (long)blockIdx.x * RB * KC);
        #pragma unroll
        for (int j = 0; j < 15; j++) {
            int i   = tid + j * 256;
            int row = i / 120;
            int c4  = i - row * 120;
            ((float4*)st)[row * (WF_PAD / 4) + c4] = __ldcs(src + i);
        }
    }
    __syncthreads();

    const int dc = w * 4;
    const ulonglong2* fw = (const ulonglong2*)(st + lane * WF_PAD);
    const unsigned long long* wp = g_wp;

    unsigned long long a0e = 0, a1e = 0, a2e = 0, a3e = 0;
    unsigned long long a0o = 0, a1o = 0, a2o = 0, a3o = 0;

    #pragma unroll 4
    for (int kq = 0; kq < KC / 4; kq++) {
        ulonglong2 f = fw[kq];   // f.x = (wf[4kq], wf[4kq+1]), f.y = (wf[4kq+2], wf[4kq+3])
        ulonglong2 we = *(const ulonglong2*)(wp + (2 * kq) * COUT + dc);       // pair p=2kq, cols dc,dc+1
        ulonglong2 wE = *(const ulonglong2*)(wp + (2 * kq) * COUT + dc + 2);   // cols dc+2,dc+3
        ulonglong2 wo = *(const ulonglong2*)(wp + (2 * kq + 1) * COUT + dc);
        ulonglong2 wO = *(const ulonglong2*)(wp + (2 * kq + 1) * COUT + dc + 2);
        fma2(a0e, f.x, we.x);
        fma2(a1e, f.x, we.y);
        fma2(a2e, f.x, wE.x);
        fma2(a3e, f.x, wE.y);
        fma2(a0o, f.y, wo.x);
        fma2(a1o, f.y, wo.y);
        fma2(a2o, f.y, wO.x);
        fma2(a3o, f.y, wO.y);
    }

    float4 o;
    o.x = (lo32(a0e) + hi32(a0e)) + (lo32(a0o) + hi32(a0o));
    o.y = (lo32(a1e) + hi32(a1e)) + (lo32(a1o) + hi32(a1o));
    o.z = (lo32(a2e) + hi32(a2e)) + (lo32(a2o) + hi32(a2o));
    o.w = (lo32(a3e) + hi32(a3e)) + (lo32(a3o) + hi32(a3o));
    *(float4*)(out + ((long)blockIdx.x * RB + lane) * COUT + dc) = o;
}

extern "C" void kernel_launch(void* const* d_in, const int* in_sizes, int n_in,
                              void* d_out, int out_size) {
    const float* q_pts   = (const float*)d_in[0];
    const float* s_pts   = (const float*)d_in[1];
    const int*   nbr     = (const int*)  d_in[2];
    const float* x       = (const float*)d_in[3];
    const float* kp      = (const float*)d_in[4];
    const float* anchors = (const float*)d_in[5];
    const float* weights = (const float*)d_in[6];
    float* out = (float*)d_out;

    const int Nq = in_sizes[2] / NB;   // 16000

    constexpr size_t smemB = (size_t)RB * WF_PAD * sizeof(float);   // 61952 B
    static bool attr_set = false;
    if (!attr_set) {
        cudaFuncSetAttribute(stage2_kernel,
                             cudaFuncAttributeMaxDynamicSharedMemorySize,
                             (int)smemB);
        attr_set = true;
    }

    precompute_kernel<<<1, 256>>>(kp, anchors, weights);
    stage1_kernel<<<Nq / QB, 256>>>(q_pts, s_pts, nbr, x);
    stage2_kernel<<<(Nq * A) / RB, 256, smemB>>>(out);
}